// round 6
// baseline (speedup 1.0000x reference)
#include <cuda_runtime.h>

#define B_ROWS 32768
#define D_IN   200
#define K_SAMP 10
#define TM     32
#define APAD   36

__device__ float g_logits[(size_t)B_ROWS * D_IN];

// smem (floats): XsT[200][36] | H1T[100][36] | WS (pair-duplicated weights)
#define OFF_X  0
#define OFF_H1 (200 * APAD)                  // 7200
#define OFF_WS (OFF_H1 + 100 * APAD)         // 10800
#define WS_FLOATS 6272                       // max(128*44, 224*28)
#define SMEM_FLOATS (OFF_WS + WS_FLOATS)     // 17072 -> 68288 B

typedef unsigned long long ull;

__device__ __forceinline__ ull pack2(float lo, float hi) {
    ull r; asm("mov.b64 %0, {%1, %2};" : "=l"(r) : "f"(lo), "f"(hi)); return r;
}
__device__ __forceinline__ void unpack2(ull v, float& lo, float& hi) {
    asm("mov.b64 {%0, %1}, %2;" : "=f"(lo), "=f"(hi) : "l"(v));
}
__device__ __forceinline__ ull fma2(ull a, ull b, ull c) {
    ull d; asm("fma.rn.f32x2 %0, %1, %2, %3;" : "=l"(d) : "l"(a), "l"(b), "l"(c)); return d;
}
__device__ __forceinline__ ull mul2(ull a, ull b) {
    ull d; asm("mul.rn.f32x2 %0, %1, %2;" : "=l"(d) : "l"(a), "l"(b)); return d;
}
__device__ __forceinline__ ull add2(ull a, ull b) {
    ull d; asm("add.rn.f32x2 %0, %1, %2;" : "=l"(d) : "l"(a), "l"(b)); return d;
}
__device__ __forceinline__ float frcp(float x) {
    float r; asm("rcp.approx.f32 %0, %1;" : "=f"(r) : "f"(x)); return r;
}
__device__ __forceinline__ float flg2(float x) {
    float r; asm("lg2.approx.f32 %0, %1;" : "=f"(r) : "f"(x)); return r;
}

// ---- one layer over 32 rows; A in smem [K][APAD]; 8 warps x 4 rows ----
// Weights staged pair-duplicated: ws[col*SD + 2kk] = ws[..+1] = W[kk][col]
template <int K, int N, int CI, int BK, int SD, bool RELU, bool TOGLOBAL>
__device__ __forceinline__ void layer(float* smem, const float* Asm,
                                      const float* __restrict__ Wg,
                                      const float* __restrict__ bg,
                                      float* Hsm, float* __restrict__ Gout,
                                      int tid) {
    constexpr int NLD = (BK * N + 255) / 256;
    float* ws = smem + OFF_WS;
    const int lane = tid & 31;
    const int wy = tid >> 5;   // rows [4wy, 4wy+4)

    ull acc[2][CI];
#pragma unroll
    for (int r = 0; r < 2; r++)
#pragma unroll
        for (int c = 0; c < CI; c++) acc[r][c] = 0ull;

    float pf[NLD];
#pragma unroll
    for (int i = 0; i < NLD; i++) {
        int idx = tid + 256 * i;
        if (idx < BK * N) pf[i] = Wg[idx];
    }
    __syncthreads();
#pragma unroll
    for (int i = 0; i < NLD; i++) {
        int idx = tid + 256 * i;
        if (idx < BK * N) {
            int kk = idx / N, c = idx - kk * N;
            *(float2*)&ws[c * SD + 2 * kk] = make_float2(pf[i], pf[i]);
        }
    }
    __syncthreads();

    for (int k0 = 0; k0 < K; k0 += BK) {
        const bool more = (k0 + BK) < K;
        if (more) {
            const float* wn = Wg + (size_t)(k0 + BK) * N;
#pragma unroll
            for (int i = 0; i < NLD; i++) {
                int idx = tid + 256 * i;
                if (idx < BK * N) pf[i] = wn[idx];
            }
        }
        const float* abase = Asm + k0 * APAD + wy * 4;
#pragma unroll
        for (int kk = 0; kk < BK; kk += 2) {
            ulonglong2 bw[CI];
#pragma unroll
            for (int c = 0; c < CI; c++)
                bw[c] = *(const ulonglong2*)&ws[(lane + 32 * c) * SD + 2 * kk];
            ulonglong2 a0 = *(const ulonglong2*)(abase + kk * APAD);
            ulonglong2 a1 = *(const ulonglong2*)(abase + (kk + 1) * APAD);
#pragma unroll
            for (int c = 0; c < CI; c++) {
                acc[0][c] = fma2(a0.x, bw[c].x, acc[0][c]);
                acc[1][c] = fma2(a0.y, bw[c].x, acc[1][c]);
                acc[0][c] = fma2(a1.x, bw[c].y, acc[0][c]);
                acc[1][c] = fma2(a1.y, bw[c].y, acc[1][c]);
            }
        }
        if (more) {
            __syncthreads();
#pragma unroll
            for (int i = 0; i < NLD; i++) {
                int idx = tid + 256 * i;
                if (idx < BK * N) {
                    int kk = idx / N, c = idx - kk * N;
                    *(float2*)&ws[c * SD + 2 * kk] = make_float2(pf[i], pf[i]);
                }
            }
            __syncthreads();
        }
    }

#pragma unroll
    for (int c = 0; c < CI; c++) {
        int col = lane + 32 * c;
        if (col < N) {
            float bv = bg[col];
#pragma unroll
            for (int r = 0; r < 2; r++) {
                float lo, hi;
                unpack2(acc[r][c], lo, hi);
                lo += bv; hi += bv;
                if (RELU) { lo = fmaxf(lo, 0.0f); hi = fmaxf(hi, 0.0f); }
                int row = wy * 4 + 2 * r;
                if (TOGLOBAL) {
                    Gout[(size_t)row * N + col] = lo;
                    Gout[(size_t)(row + 1) * N + col] = hi;
                } else {
                    *(float2*)&Hsm[col * APAD + row] = make_float2(lo, hi);
                }
            }
        }
    }
}

__global__ __launch_bounds__(256, 3) void mlp_kernel(
    const float* __restrict__ x,
    const float* __restrict__ w1, const float* __restrict__ b1,
    const float* __restrict__ w2, const float* __restrict__ b2,
    const float* __restrict__ wl, const float* __restrict__ bl,
    float* __restrict__ logits) {
    extern __shared__ float smem[];
    const int tid = threadIdx.x;
    const int rowBase = blockIdx.x * TM;

    {
        const float4* xb = (const float4*)(x + (size_t)rowBase * D_IN);
        for (int it = tid; it < 32 * 50; it += 256) {
            int q = it >> 5, row = it & 31;
            float4 v = xb[row * 50 + q];
            float* p = smem + OFF_X + (4 * q) * APAD + row;
            p[0] = v.x; p[APAD] = v.y; p[2 * APAD] = v.z; p[3 * APAD] = v.w;
        }
    }
    layer<200, 100, 4, 20, 44, true, false>(smem, smem + OFF_X, w1, b1, smem + OFF_H1, nullptr, tid);
    layer<100, 100, 4, 20, 44, true, false>(smem, smem + OFF_H1, w2, b2, smem + OFF_H1, nullptr, tid);
    layer<100, 200, 7, 10, 28, false, true>(smem, smem + OFF_H1, wl, bl, nullptr,
                                            logits + (size_t)rowBase * D_IN, tid);
}

// ---- sampler: one warp per row; w_i = E_i / lg2(u_i)^2 (constants cancel in ratio) ----
__device__ __forceinline__ void load8(float* dst, const float* src, bool act) {
    if (act) {
        float4 a = *(const float4*)src;
        float4 b = *(const float4*)(src + 4);
        dst[0] = a.x; dst[1] = a.y; dst[2] = a.z; dst[3] = a.w;
        dst[4] = b.x; dst[5] = b.y; dst[6] = b.z; dst[7] = b.w;
    } else {
#pragma unroll
        for (int i = 0; i < 8; i++) dst[i] = 0.5f;
    }
}

__global__ __launch_bounds__(256, 4) void sample_kernel(
    const float* __restrict__ x, const float* __restrict__ uniform,
    const float* __restrict__ logits,
    const float* __restrict__ wo, const float* __restrict__ bo,
    float* __restrict__ preds, float* __restrict__ samples) {
    const int b = (blockIdx.x * 256 + threadIdx.x) >> 5;
    const int lane = threadIdx.x & 31;
    const bool act = lane < 25;
    const int d0 = 8 * lane;
    constexpr float EPSF = 1.1920929e-07f;

    // poly for log2(1+xm), |xm| <= 0.01:  xm*(c1 + c2*xm + c3*xm^2)
    const ull C1 = pack2(1.44269504f, 1.44269504f);
    const ull C2 = pack2(-0.72134752f, -0.72134752f);
    const ull C3 = pack2(0.48089835f, 0.48089835f);
    const ull M1 = pack2(-1.0f, -1.0f);

    ull Epk[4];
    float smp[8];
    {
        float lg[8];
        if (act) load8(lg, &logits[(size_t)b * D_IN + d0], true);
        else {
#pragma unroll
            for (int i = 0; i < 8; i++) lg[i] = -1e30f;
        }
        float m = lg[0];
#pragma unroll
        for (int i = 1; i < 8; i++) m = fmaxf(m, lg[i]);
#pragma unroll
        for (int off = 16; off > 0; off >>= 1)
            m = fmaxf(m, __shfl_xor_sync(0xffffffffu, m, off));
#pragma unroll
        for (int j = 0; j < 4; j++) {
            float e0 = act ? __expf(2.0f * (lg[2 * j] - m)) : 0.0f;
            float e1 = act ? __expf(2.0f * (lg[2 * j + 1] - m)) : 0.0f;
            Epk[j] = pack2(e0, e1);
        }
#pragma unroll
        for (int i = 0; i < 8; i++) smp[i] = 0.0f;
    }

    const float* up = uniform + (size_t)b * (K_SAMP * D_IN) + d0;
    float cu[8];
    load8(cu, up, act);

#pragma unroll
    for (int k = 0; k < K_SAMP; k++) {
        float nu[8];
        if (k < K_SAMP - 1) load8(nu, up + (k + 1) * D_IN, act);
        ull wv[4];
        ull sacc = 0ull;
#pragma unroll
        for (int j = 0; j < 4; j++) {
            float u0 = fmaxf(cu[2 * j], EPSF);
            float u1 = fmaxf(cu[2 * j + 1], EPSF);
            float l0 = flg2(u0);          // MUFU; |l| = |log2 u|
            float l1 = flg2(u1);
            ull upk = pack2(u0, u1);
            ull xm = add2(upk, M1);       // u - 1 (exact near 1)
            ull q = fma2(xm, fma2(xm, C3, C2), C1);
            ull pp = mul2(xm, q);         // accurate log2(1+xm) for u near 1
            float p0, p1;
            unpack2(pp, p0, p1);
            float t0 = (u0 > 0.99f) ? p0 : l0;
            float t1 = (u1 > 0.99f) ? p1 : l1;
            ull tt = pack2(t0, t1);
            ull t2 = mul2(tt, tt);        // sign-free: only magnitude matters
            float s0, s1;
            unpack2(t2, s0, s1);
            ull rr = pack2(frcp(s0), frcp(s1));  // MUFU rcp
            ull w = mul2(Epk[j], rr);     // E / lg2(u)^2
            wv[j] = w;
            sacc = add2(sacc, w);
        }
        float sl, sh;
        unpack2(sacc, sl, sh);
        float s = sl + sh;
#pragma unroll
        for (int off = 16; off > 0; off >>= 1)
            s += __shfl_xor_sync(0xffffffffu, s, off);
        ull ipk;
        {
            float inv = frcp(s);
            ipk = pack2(inv, inv);
        }
#pragma unroll
        for (int j = 0; j < 4; j++) {
            ull wi = mul2(wv[j], ipk);
            float a0, a1;
            unpack2(wi, a0, a1);
            smp[2 * j] = fmaxf(smp[2 * j], a0);
            smp[2 * j + 1] = fmaxf(smp[2 * j + 1], a1);
        }
        if (k < K_SAMP - 1) {
#pragma unroll
            for (int i = 0; i < 8; i++) cu[i] = nu[i];
        }
    }

    if (act) {
        *(float4*)&samples[(size_t)b * D_IN + d0] =
            make_float4(smp[0], smp[1], smp[2], smp[3]);
        *(float4*)&samples[(size_t)b * D_IN + d0 + 4] =
            make_float4(smp[4], smp[5], smp[6], smp[7]);
    }

    float p0 = 0.0f, p1 = 0.0f;
    if (act) {
        float xv[8];
        load8(xv, &x[(size_t)b * D_IN + d0], true);
#pragma unroll
        for (int i = 0; i < 8; i += 2) {
            float4 w4 = *(const float4*)&wo[(d0 + i) * 2];
            float a0 = xv[i] * smp[i], a1 = xv[i + 1] * smp[i + 1];
            p0 += a0 * w4.x + a1 * w4.z;
            p1 += a0 * w4.y + a1 * w4.w;
        }
    }
#pragma unroll
    for (int off = 16; off > 0; off >>= 1) {
        p0 += __shfl_xor_sync(0xffffffffu, p0, off);
        p1 += __shfl_xor_sync(0xffffffffu, p1, off);
    }
    if (lane == 0) {
        p0 += bo[0]; p1 += bo[1];
        float mm = fmaxf(p0, p1);
        float e0 = __expf(p0 - mm), e1 = __expf(p1 - mm);
        float is = 1.0f / (e0 + e1);
        preds[(size_t)b * 2 + 0] = e0 * is;
        preds[(size_t)b * 2 + 1] = e1 * is;
    }
}

extern "C" void kernel_launch(void* const* d_in, const int* in_sizes, int n_in,
                              void* d_out, int out_size) {
    const float* x  = (const float*)d_in[0];
    const float* un = (const float*)d_in[1];
    const float* w1 = (const float*)d_in[2];
    const float* b1 = (const float*)d_in[3];
    const float* w2 = (const float*)d_in[4];
    const float* b2 = (const float*)d_in[5];
    const float* wl = (const float*)d_in[6];
    const float* bl = (const float*)d_in[7];
    const float* wo = (const float*)d_in[8];
    const float* bo = (const float*)d_in[9];
    float* out = (float*)d_out;

    float* lgts;
    cudaGetSymbolAddress((void**)&lgts, g_logits);

    const int smem_bytes = SMEM_FLOATS * (int)sizeof(float);  // 68288
    cudaFuncSetAttribute(mlp_kernel, cudaFuncAttributeMaxDynamicSharedMemorySize, smem_bytes);

    mlp_kernel<<<B_ROWS / TM, 256, smem_bytes>>>(x, w1, b1, w2, b2, wl, bl, lgts);
    sample_kernel<<<B_ROWS / 8, 256>>>(x, un, lgts, wo, bo,
                                       out, out + (size_t)B_ROWS * 2);
}

// round 7
// speedup vs baseline: 1.0057x; 1.0057x over previous
#include <cuda_runtime.h>

#define B_ROWS 32768
#define D_IN   200
#define K_SAMP 10
#define TM     32
#define APAD   36

__device__ float g_logits[(size_t)B_ROWS * D_IN];

// smem (floats): XsT[200][36] | H1T[100][36] | WS (pair-duplicated weights)
#define OFF_X  0
#define OFF_H1 (200 * APAD)                  // 7200
#define OFF_WS (OFF_H1 + 100 * APAD)         // 10800
#define WS_FLOATS 6272                       // max(128*44, 224*28)
#define SMEM_FLOATS (OFF_WS + WS_FLOATS)     // 17072 -> 68288 B

typedef unsigned long long ull;

__device__ __forceinline__ ull pack2(float lo, float hi) {
    ull r; asm("mov.b64 %0, {%1, %2};" : "=l"(r) : "f"(lo), "f"(hi)); return r;
}
__device__ __forceinline__ void unpack2(ull v, float& lo, float& hi) {
    asm("mov.b64 {%0, %1}, %2;" : "=f"(lo), "=f"(hi) : "l"(v));
}
__device__ __forceinline__ ull fma2(ull a, ull b, ull c) {
    ull d; asm("fma.rn.f32x2 %0, %1, %2, %3;" : "=l"(d) : "l"(a), "l"(b), "l"(c)); return d;
}
__device__ __forceinline__ ull mul2(ull a, ull b) {
    ull d; asm("mul.rn.f32x2 %0, %1, %2;" : "=l"(d) : "l"(a), "l"(b)); return d;
}
__device__ __forceinline__ ull add2(ull a, ull b) {
    ull d; asm("add.rn.f32x2 %0, %1, %2;" : "=l"(d) : "l"(a), "l"(b)); return d;
}
__device__ __forceinline__ float frcp(float x) {
    float r; asm("rcp.approx.f32 %0, %1;" : "=f"(r) : "f"(x)); return r;
}
__device__ __forceinline__ float flg2(float x) {
    float r; asm("lg2.approx.f32 %0, %1;" : "=f"(r) : "f"(x)); return r;
}

// ---- one layer over 32 rows; A in smem [K][APAD]; 8 warps x 4 rows ----
// Weights staged pair-duplicated: ws[col*SD + 2kk] = ws[..+1] = W[kk][col]
template <int K, int N, int CI, int BK, int SD, bool RELU, bool TOGLOBAL>
__device__ __forceinline__ void layer(float* smem, const float* Asm,
                                      const float* __restrict__ Wg,
                                      const float* __restrict__ bg,
                                      float* Hsm, float* __restrict__ Gout,
                                      int tid) {
    constexpr int NLD = (BK * N + 255) / 256;
    float* ws = smem + OFF_WS;
    const int lane = tid & 31;
    const int wy = tid >> 5;   // rows [4wy, 4wy+4)

    ull acc[2][CI];
#pragma unroll
    for (int r = 0; r < 2; r++)
#pragma unroll
        for (int c = 0; c < CI; c++) acc[r][c] = 0ull;

    float pf[NLD];
#pragma unroll
    for (int i = 0; i < NLD; i++) {
        int idx = tid + 256 * i;
        if (idx < BK * N) pf[i] = Wg[idx];
    }
    __syncthreads();
#pragma unroll
    for (int i = 0; i < NLD; i++) {
        int idx = tid + 256 * i;
        if (idx < BK * N) {
            int kk = idx / N, c = idx - kk * N;
            *(float2*)&ws[c * SD + 2 * kk] = make_float2(pf[i], pf[i]);
        }
    }
    __syncthreads();

    for (int k0 = 0; k0 < K; k0 += BK) {
        const bool more = (k0 + BK) < K;
        if (more) {
            const float* wn = Wg + (size_t)(k0 + BK) * N;
#pragma unroll
            for (int i = 0; i < NLD; i++) {
                int idx = tid + 256 * i;
                if (idx < BK * N) pf[i] = wn[idx];
            }
        }
        const float* abase = Asm + k0 * APAD + wy * 4;
#pragma unroll
        for (int kk = 0; kk < BK; kk += 2) {
            ulonglong2 bw[CI];
#pragma unroll
            for (int c = 0; c < CI; c++)
                bw[c] = *(const ulonglong2*)&ws[(lane + 32 * c) * SD + 2 * kk];
            ulonglong2 a0 = *(const ulonglong2*)(abase + kk * APAD);
            ulonglong2 a1 = *(const ulonglong2*)(abase + (kk + 1) * APAD);
#pragma unroll
            for (int c = 0; c < CI; c++) {
                acc[0][c] = fma2(a0.x, bw[c].x, acc[0][c]);
                acc[1][c] = fma2(a0.y, bw[c].x, acc[1][c]);
                acc[0][c] = fma2(a1.x, bw[c].y, acc[0][c]);
                acc[1][c] = fma2(a1.y, bw[c].y, acc[1][c]);
            }
        }
        if (more) {
            __syncthreads();
#pragma unroll
            for (int i = 0; i < NLD; i++) {
                int idx = tid + 256 * i;
                if (idx < BK * N) {
                    int kk = idx / N, c = idx - kk * N;
                    *(float2*)&ws[c * SD + 2 * kk] = make_float2(pf[i], pf[i]);
                }
            }
            __syncthreads();
        }
    }

#pragma unroll
    for (int c = 0; c < CI; c++) {
        int col = lane + 32 * c;
        if (col < N) {
            float bv = bg[col];
#pragma unroll
            for (int r = 0; r < 2; r++) {
                float lo, hi;
                unpack2(acc[r][c], lo, hi);
                lo += bv; hi += bv;
                if (RELU) { lo = fmaxf(lo, 0.0f); hi = fmaxf(hi, 0.0f); }
                int row = wy * 4 + 2 * r;
                if (TOGLOBAL) {
                    Gout[(size_t)row * N + col] = lo;
                    Gout[(size_t)(row + 1) * N + col] = hi;
                } else {
                    *(float2*)&Hsm[col * APAD + row] = make_float2(lo, hi);
                }
            }
        }
    }
}

__global__ __launch_bounds__(256, 3) void mlp_kernel(
    const float* __restrict__ x,
    const float* __restrict__ w1, const float* __restrict__ b1,
    const float* __restrict__ w2, const float* __restrict__ b2,
    const float* __restrict__ wl, const float* __restrict__ bl,
    float* __restrict__ logits) {
    extern __shared__ float smem[];
    const int tid = threadIdx.x;
    const int rowBase = blockIdx.x * TM;

    {
        const float4* xb = (const float4*)(x + (size_t)rowBase * D_IN);
        for (int it = tid; it < 32 * 50; it += 256) {
            int q = it >> 5, row = it & 31;
            float4 v = xb[row * 50 + q];
            float* p = smem + OFF_X + (4 * q) * APAD + row;
            p[0] = v.x; p[APAD] = v.y; p[2 * APAD] = v.z; p[3 * APAD] = v.w;
        }
    }
    layer<200, 100, 4, 20, 44, true, false>(smem, smem + OFF_X, w1, b1, smem + OFF_H1, nullptr, tid);
    layer<100, 100, 4, 20, 44, true, false>(smem, smem + OFF_H1, w2, b2, smem + OFF_H1, nullptr, tid);
    layer<100, 200, 7, 10, 28, false, true>(smem, smem + OFF_H1, wl, bl, nullptr,
                                            logits + (size_t)rowBase * D_IN, tid);
}

// ---- sampler: one warp per row; w_i = E_i / lg2(u_i)^2 (constants cancel in ratio) ----
__device__ __forceinline__ void load8(float* dst, const float* src, bool act) {
    if (act) {
        float4 a = *(const float4*)src;
        float4 b = *(const float4*)(src + 4);
        dst[0] = a.x; dst[1] = a.y; dst[2] = a.z; dst[3] = a.w;
        dst[4] = b.x; dst[5] = b.y; dst[6] = b.z; dst[7] = b.w;
    } else {
#pragma unroll
        for (int i = 0; i < 8; i++) dst[i] = 0.5f;
    }
}

__global__ __launch_bounds__(256, 4) void sample_kernel(
    const float* __restrict__ x, const float* __restrict__ uniform,
    const float* __restrict__ logits,
    const float* __restrict__ wo, const float* __restrict__ bo,
    float* __restrict__ preds, float* __restrict__ samples) {
    const int b = (blockIdx.x * 256 + threadIdx.x) >> 5;
    const int lane = threadIdx.x & 31;
    const bool act = lane < 25;
    const int d0 = 8 * lane;
    constexpr float EPSF = 1.1920929e-07f;

    // poly for log2(1+xm), |xm| <= 0.01:  xm*(c1 + c2*xm + c3*xm^2)
    const ull C1 = pack2(1.44269504f, 1.44269504f);
    const ull C2 = pack2(-0.72134752f, -0.72134752f);
    const ull C3 = pack2(0.48089835f, 0.48089835f);
    const ull M1 = pack2(-1.0f, -1.0f);

    ull Epk[4];
    float smp[8];
    {
        float lg[8];
        if (act) load8(lg, &logits[(size_t)b * D_IN + d0], true);
        else {
#pragma unroll
            for (int i = 0; i < 8; i++) lg[i] = -1e30f;
        }
        float m = lg[0];
#pragma unroll
        for (int i = 1; i < 8; i++) m = fmaxf(m, lg[i]);
#pragma unroll
        for (int off = 16; off > 0; off >>= 1)
            m = fmaxf(m, __shfl_xor_sync(0xffffffffu, m, off));
#pragma unroll
        for (int j = 0; j < 4; j++) {
            float e0 = act ? __expf(2.0f * (lg[2 * j] - m)) : 0.0f;
            float e1 = act ? __expf(2.0f * (lg[2 * j + 1] - m)) : 0.0f;
            Epk[j] = pack2(e0, e1);
        }
#pragma unroll
        for (int i = 0; i < 8; i++) smp[i] = 0.0f;
    }

    const float* up = uniform + (size_t)b * (K_SAMP * D_IN) + d0;
    float cu[8];
    load8(cu, up, act);

#pragma unroll
    for (int k = 0; k < K_SAMP; k++) {
        float nu[8];
        if (k < K_SAMP - 1) load8(nu, up + (k + 1) * D_IN, act);
        ull wv[4];
        ull sacc = 0ull;
#pragma unroll
        for (int j = 0; j < 4; j++) {
            float u0 = fmaxf(cu[2 * j], EPSF);
            float u1 = fmaxf(cu[2 * j + 1], EPSF);
            float l0 = flg2(u0);          // MUFU; |l| = |log2 u|
            float l1 = flg2(u1);
            ull upk = pack2(u0, u1);
            ull xm = add2(upk, M1);       // u - 1 (exact near 1)
            ull q = fma2(xm, fma2(xm, C3, C2), C1);
            ull pp = mul2(xm, q);         // accurate log2(1+xm) for u near 1
            float p0, p1;
            unpack2(pp, p0, p1);
            float t0 = (u0 > 0.99f) ? p0 : l0;
            float t1 = (u1 > 0.99f) ? p1 : l1;
            ull tt = pack2(t0, t1);
            ull t2 = mul2(tt, tt);        // sign-free: only magnitude matters
            float s0, s1;
            unpack2(t2, s0, s1);
            ull rr = pack2(frcp(s0), frcp(s1));  // MUFU rcp
            ull w = mul2(Epk[j], rr);     // E / lg2(u)^2
            wv[j] = w;
            sacc = add2(sacc, w);
        }
        float sl, sh;
        unpack2(sacc, sl, sh);
        float s = sl + sh;
#pragma unroll
        for (int off = 16; off > 0; off >>= 1)
            s += __shfl_xor_sync(0xffffffffu, s, off);
        ull ipk;
        {
            float inv = frcp(s);
            ipk = pack2(inv, inv);
        }
#pragma unroll
        for (int j = 0; j < 4; j++) {
            ull wi = mul2(wv[j], ipk);
            float a0, a1;
            unpack2(wi, a0, a1);
            smp[2 * j] = fmaxf(smp[2 * j], a0);
            smp[2 * j + 1] = fmaxf(smp[2 * j + 1], a1);
        }
        if (k < K_SAMP - 1) {
#pragma unroll
            for (int i = 0; i < 8; i++) cu[i] = nu[i];
        }
    }

    if (act) {
        *(float4*)&samples[(size_t)b * D_IN + d0] =
            make_float4(smp[0], smp[1], smp[2], smp[3]);
        *(float4*)&samples[(size_t)b * D_IN + d0 + 4] =
            make_float4(smp[4], smp[5], smp[6], smp[7]);
    }

    float p0 = 0.0f, p1 = 0.0f;
    if (act) {
        float xv[8];
        load8(xv, &x[(size_t)b * D_IN + d0], true);
#pragma unroll
        for (int i = 0; i < 8; i += 2) {
            float4 w4 = *(const float4*)&wo[(d0 + i) * 2];
            float a0 = xv[i] * smp[i], a1 = xv[i + 1] * smp[i + 1];
            p0 += a0 * w4.x + a1 * w4.z;
            p1 += a0 * w4.y + a1 * w4.w;
        }
    }
#pragma unroll
    for (int off = 16; off > 0; off >>= 1) {
        p0 += __shfl_xor_sync(0xffffffffu, p0, off);
        p1 += __shfl_xor_sync(0xffffffffu, p1, off);
    }
    if (lane == 0) {
        p0 += bo[0]; p1 += bo[1];
        float mm = fmaxf(p0, p1);
        float e0 = __expf(p0 - mm), e1 = __expf(p1 - mm);
        float is = 1.0f / (e0 + e1);
        preds[(size_t)b * 2 + 0] = e0 * is;
        preds[(size_t)b * 2 + 1] = e1 * is;
    }
}

extern "C" void kernel_launch(void* const* d_in, const int* in_sizes, int n_in,
                              void* d_out, int out_size) {
    const float* x  = (const float*)d_in[0];
    const float* un = (const float*)d_in[1];
    const float* w1 = (const float*)d_in[2];
    const float* b1 = (const float*)d_in[3];
    const float* w2 = (const float*)d_in[4];
    const float* b2 = (const float*)d_in[5];
    const float* wl = (const float*)d_in[6];
    const float* bl = (const float*)d_in[7];
    const float* wo = (const float*)d_in[8];
    const float* bo = (const float*)d_in[9];
    float* out = (float*)d_out;

    float* lgts;
    cudaGetSymbolAddress((void**)&lgts, g_logits);

    const int smem_bytes = SMEM_FLOATS * (int)sizeof(float);  // 68288
    cudaFuncSetAttribute(mlp_kernel, cudaFuncAttributeMaxDynamicSharedMemorySize, smem_bytes);

    mlp_kernel<<<B_ROWS / TM, 256, smem_bytes>>>(x, w1, b1, w2, b2, wl, bl, lgts);
    sample_kernel<<<B_ROWS / 8, 256>>>(x, un, lgts, wo, bo,
                                       out, out + (size_t)B_ROWS * 2);
}

// round 8
// speedup vs baseline: 1.3324x; 1.3249x over previous
#include <cuda_runtime.h>

#define B_ROWS 32768
#define D_IN   200
#define K_SAMP 10
#define TM     64
#define APAD   68

__device__ float g_logits[(size_t)B_ROWS * D_IN];

// smem (floats): XsT[200][68] | H1T[100][68] (layer2 in-place) | WS double-buffer
#define OFF_X  0
#define OFF_H1 (200 * APAD)            // 13600
#define OFF_WS (OFF_H1 + 100 * APAD)   // 20400
#define WSLOT  2560                    // per-slot floats: max(128*20, 224*10)
#define SMEM_FLOATS (OFF_WS + 2 * WSLOT)  // 25520 floats = 102080 B

typedef unsigned long long ull;

__device__ __forceinline__ ull pack2(float lo, float hi) {
    ull r; asm("mov.b64 %0, {%1, %2};" : "=l"(r) : "f"(lo), "f"(hi)); return r;
}
__device__ __forceinline__ ull dup2(float w) {
    ull r; asm("mov.b64 %0, {%1, %1};" : "=l"(r) : "f"(w)); return r;
}
__device__ __forceinline__ void unpack2(ull v, float& lo, float& hi) {
    asm("mov.b64 {%0, %1}, %2;" : "=f"(lo), "=f"(hi) : "l"(v));
}
__device__ __forceinline__ ull fma2(ull a, ull b, ull c) {
    ull d; asm("fma.rn.f32x2 %0, %1, %2, %3;" : "=l"(d) : "l"(a), "l"(b), "l"(c)); return d;
}
__device__ __forceinline__ ull mul2(ull a, ull b) {
    ull d; asm("mul.rn.f32x2 %0, %1, %2;" : "=l"(d) : "l"(a), "l"(b)); return d;
}
__device__ __forceinline__ ull add2(ull a, ull b) {
    ull d; asm("add.rn.f32x2 %0, %1, %2;" : "=l"(d) : "l"(a), "l"(b)); return d;
}
__device__ __forceinline__ float frcp(float x) {
    float r; asm("rcp.approx.f32 %0, %1;" : "=f"(r) : "f"(x)); return r;
}
__device__ __forceinline__ float flg2(float x) {
    float r; asm("lg2.approx.f32 %0, %1;" : "=f"(r) : "f"(x)); return r;
}

// ---- one layer over 64 rows; A in smem [K][APAD]; 8 warps x 8 rows ----
// ws slot layout: ws[col*BK + kk]; double-buffered, ONE bar per chunk.
template <int K, int N, int CI, int BK, bool RELU, bool TOGLOBAL>
__device__ __forceinline__ void layer(float* smem, const float* Asm,
                                      const float* __restrict__ Wg,
                                      const float* __restrict__ bg,
                                      float* Hsm, float* __restrict__ Gout,
                                      int tid) {
    constexpr int KSTEP = (BK % 4 == 0) ? 4 : 2;
    constexpr int NLD = (BK * N + 255) / 256;
    constexpr int NCH = K / BK;
    const int lane = tid & 31;
    const int wy = tid >> 5;   // rows [8wy, 8wy+8)

    ull acc[4][CI];
#pragma unroll
    for (int r = 0; r < 4; r++)
#pragma unroll
        for (int c = 0; c < CI; c++) acc[r][c] = 0ull;

    float pf[NLD];
#pragma unroll
    for (int i = 0; i < NLD; i++) {
        int idx = tid + 256 * i;
        if (idx < BK * N) pf[i] = Wg[idx];
    }
    __syncthreads();   // prev layer done with WS slots & Asm writes visible
    {
        float* ws0 = smem + OFF_WS;
#pragma unroll
        for (int i = 0; i < NLD; i++) {
            int idx = tid + 256 * i;
            if (idx < BK * N) { int kk = idx / N, c = idx - kk * N; ws0[c * BK + kk] = pf[i]; }
        }
    }
    __syncthreads();

    for (int ch = 0; ch < NCH; ch++) {
        const float* cur = smem + OFF_WS + (ch & 1) * WSLOT;
        const bool more = (ch + 1) < NCH;
        if (more) {
            const float* wn = Wg + (size_t)(ch + 1) * BK * N;
#pragma unroll
            for (int i = 0; i < NLD; i++) {
                int idx = tid + 256 * i;
                if (idx < BK * N) pf[i] = wn[idx];
            }
        }
        const float* abase = Asm + ch * BK * APAD + wy * 8;
#pragma unroll
        for (int kk = 0; kk < BK; kk += KSTEP) {
            float wv[CI][KSTEP];
#pragma unroll
            for (int c = 0; c < CI; c++) {
                const float* wp_ = &cur[(lane + 32 * c) * BK + kk];
                if (KSTEP == 4) {
                    float4 v = *(const float4*)wp_;
                    wv[c][0] = v.x; wv[c][1] = v.y; wv[c][2] = v.z; wv[c][3] = v.w;
                } else {
                    float2 v = *(const float2*)wp_;
                    wv[c][0] = v.x; wv[c][1] = v.y;
                }
            }
#pragma unroll
            for (int j = 0; j < KSTEP; j++) {
                const float* arow = abase + (kk + j) * APAD;
                ulonglong2 a01 = *(const ulonglong2*)arow;
                ulonglong2 a23 = *(const ulonglong2*)(arow + 4);
#pragma unroll
                for (int c = 0; c < CI; c++) {
                    ull wp = dup2(wv[c][j]);
                    acc[0][c] = fma2(a01.x, wp, acc[0][c]);
                    acc[1][c] = fma2(a01.y, wp, acc[1][c]);
                    acc[2][c] = fma2(a23.x, wp, acc[2][c]);
                    acc[3][c] = fma2(a23.y, wp, acc[3][c]);
                }
            }
        }
        if (more) {
            float* nxt = smem + OFF_WS + ((ch + 1) & 1) * WSLOT;
#pragma unroll
            for (int i = 0; i < NLD; i++) {
                int idx = tid + 256 * i;
                if (idx < BK * N) { int kk = idx / N, c = idx - kk * N; nxt[c * BK + kk] = pf[i]; }
            }
            __syncthreads();   // single bar per chunk
        }
    }

    // epilogue: rows are warp-private -> no bar needed; in-place Hsm is safe
#pragma unroll
    for (int c = 0; c < CI; c++) {
        int col = lane + 32 * c;
        if (col < N) {
            float bv = bg[col];
#pragma unroll
            for (int r = 0; r < 4; r++) {
                float lo, hi;
                unpack2(acc[r][c], lo, hi);
                lo += bv; hi += bv;
                if (RELU) { lo = fmaxf(lo, 0.0f); hi = fmaxf(hi, 0.0f); }
                int row = wy * 8 + 2 * r;
                if (TOGLOBAL) {
                    Gout[(size_t)row * N + col] = lo;
                    Gout[(size_t)(row + 1) * N + col] = hi;
                } else {
                    *(float2*)&Hsm[col * APAD + row] = make_float2(lo, hi);
                }
            }
        }
    }
}

__global__ __launch_bounds__(256, 2) void mlp_kernel(
    const float* __restrict__ x,
    const float* __restrict__ w1, const float* __restrict__ b1,
    const float* __restrict__ w2, const float* __restrict__ b2,
    const float* __restrict__ wl, const float* __restrict__ bl,
    float* __restrict__ logits) {
    extern __shared__ float smem[];
    const int tid = threadIdx.x;
    const int rowBase = blockIdx.x * TM;

    // stage x transposed: XsT[k][row], 64 rows
    {
        const float4* xb = (const float4*)(x + (size_t)rowBase * D_IN);
        for (int it = tid; it < 64 * 50; it += 256) {
            int q = it >> 6, row = it & 63;
            float4 v = xb[row * 50 + q];
            float* p = smem + OFF_X + (4 * q) * APAD + row;
            p[0] = v.x; p[APAD] = v.y; p[2 * APAD] = v.z; p[3 * APAD] = v.w;
        }
    }
    layer<200, 100, 4, 20, true, false>(smem, smem + OFF_X, w1, b1, smem + OFF_H1, nullptr, tid);
    layer<100, 100, 4, 20, true, false>(smem, smem + OFF_H1, w2, b2, smem + OFF_H1, nullptr, tid);
    layer<100, 200, 7, 10, false, true>(smem, smem + OFF_H1, wl, bl, nullptr,
                                        logits + (size_t)rowBase * D_IN, tid);
}

// ---- sampler (R7, unchanged): w_i = E_i / lg2(u_i)^2; constants cancel in ratio ----
__device__ __forceinline__ void load8(float* dst, const float* src, bool act) {
    if (act) {
        float4 a = *(const float4*)src;
        float4 b = *(const float4*)(src + 4);
        dst[0] = a.x; dst[1] = a.y; dst[2] = a.z; dst[3] = a.w;
        dst[4] = b.x; dst[5] = b.y; dst[6] = b.z; dst[7] = b.w;
    } else {
#pragma unroll
        for (int i = 0; i < 8; i++) dst[i] = 0.5f;
    }
}

__global__ __launch_bounds__(256, 4) void sample_kernel(
    const float* __restrict__ x, const float* __restrict__ uniform,
    const float* __restrict__ logits,
    const float* __restrict__ wo, const float* __restrict__ bo,
    float* __restrict__ preds, float* __restrict__ samples) {
    const int b = (blockIdx.x * 256 + threadIdx.x) >> 5;
    const int lane = threadIdx.x & 31;
    const bool act = lane < 25;
    const int d0 = 8 * lane;
    constexpr float EPSF = 1.1920929e-07f;

    const ull C1 = pack2(1.44269504f, 1.44269504f);
    const ull C2 = pack2(-0.72134752f, -0.72134752f);
    const ull C3 = pack2(0.48089835f, 0.48089835f);
    const ull M1 = pack2(-1.0f, -1.0f);

    ull Epk[4];
    float smp[8];
    {
        float lg[8];
        if (act) load8(lg, &logits[(size_t)b * D_IN + d0], true);
        else {
#pragma unroll
            for (int i = 0; i < 8; i++) lg[i] = -1e30f;
        }
        float m = lg[0];
#pragma unroll
        for (int i = 1; i < 8; i++) m = fmaxf(m, lg[i]);
#pragma unroll
        for (int off = 16; off > 0; off >>= 1)
            m = fmaxf(m, __shfl_xor_sync(0xffffffffu, m, off));
#pragma unroll
        for (int j = 0; j < 4; j++) {
            float e0 = act ? __expf(2.0f * (lg[2 * j] - m)) : 0.0f;
            float e1 = act ? __expf(2.0f * (lg[2 * j + 1] - m)) : 0.0f;
            Epk[j] = pack2(e0, e1);
        }
#pragma unroll
        for (int i = 0; i < 8; i++) smp[i] = 0.0f;
    }

    const float* up = uniform + (size_t)b * (K_SAMP * D_IN) + d0;
    float cu[8];
    load8(cu, up, act);

#pragma unroll
    for (int k = 0; k < K_SAMP; k++) {
        float nu[8];
        if (k < K_SAMP - 1) load8(nu, up + (k + 1) * D_IN, act);
        ull wv[4];
        ull sacc = 0ull;
#pragma unroll
        for (int j = 0; j < 4; j++) {
            float u0 = fmaxf(cu[2 * j], EPSF);
            float u1 = fmaxf(cu[2 * j + 1], EPSF);
            float l0 = flg2(u0);
            float l1 = flg2(u1);
            ull upk = pack2(u0, u1);
            ull xm = add2(upk, M1);
            ull q = fma2(xm, fma2(xm, C3, C2), C1);
            ull pp = mul2(xm, q);
            float p0, p1;
            unpack2(pp, p0, p1);
            float t0 = (u0 > 0.99f) ? p0 : l0;
            float t1 = (u1 > 0.99f) ? p1 : l1;
            ull tt = pack2(t0, t1);
            ull t2 = mul2(tt, tt);
            float s0, s1;
            unpack2(t2, s0, s1);
            ull rr = pack2(frcp(s0), frcp(s1));
            ull w = mul2(Epk[j], rr);
            wv[j] = w;
            sacc = add2(sacc, w);
        }
        float sl, sh;
        unpack2(sacc, sl, sh);
        float s = sl + sh;
#pragma unroll
        for (int off = 16; off > 0; off >>= 1)
            s += __shfl_xor_sync(0xffffffffu, s, off);
        ull ipk;
        {
            float inv = frcp(s);
            ipk = pack2(inv, inv);
        }
#pragma unroll
        for (int j = 0; j < 4; j++) {
            ull wi = mul2(wv[j], ipk);
            float a0, a1;
            unpack2(wi, a0, a1);
            smp[2 * j] = fmaxf(smp[2 * j], a0);
            smp[2 * j + 1] = fmaxf(smp[2 * j + 1], a1);
        }
        if (k < K_SAMP - 1) {
#pragma unroll
            for (int i = 0; i < 8; i++) cu[i] = nu[i];
        }
    }

    if (act) {
        *(float4*)&samples[(size_t)b * D_IN + d0] =
            make_float4(smp[0], smp[1], smp[2], smp[3]);
        *(float4*)&samples[(size_t)b * D_IN + d0 + 4] =
            make_float4(smp[4], smp[5], smp[6], smp[7]);
    }

    float p0 = 0.0f, p1 = 0.0f;
    if (act) {
        float xv[8];
        load8(xv, &x[(size_t)b * D_IN + d0], true);
#pragma unroll
        for (int i = 0; i < 8; i += 2) {
            float4 w4 = *(const float4*)&wo[(d0 + i) * 2];
            float a0 = xv[i] * smp[i], a1 = xv[i + 1] * smp[i + 1];
            p0 += a0 * w4.x + a1 * w4.z;
            p1 += a0 * w4.y + a1 * w4.w;
        }
    }
#pragma unroll
    for (int off = 16; off > 0; off >>= 1) {
        p0 += __shfl_xor_sync(0xffffffffu, p0, off);
        p1 += __shfl_xor_sync(0xffffffffu, p1, off);
    }
    if (lane == 0) {
        p0 += bo[0]; p1 += bo[1];
        float mm = fmaxf(p0, p1);
        float e0 = __expf(p0 - mm), e1 = __expf(p1 - mm);
        float is = 1.0f / (e0 + e1);
        preds[(size_t)b * 2 + 0] = e0 * is;
        preds[(size_t)b * 2 + 1] = e1 * is;
    }
}

extern "C" void kernel_launch(void* const* d_in, const int* in_sizes, int n_in,
                              void* d_out, int out_size) {
    const float* x  = (const float*)d_in[0];
    const float* un = (const float*)d_in[1];
    const float* w1 = (const float*)d_in[2];
    const float* b1 = (const float*)d_in[3];
    const float* w2 = (const float*)d_in[4];
    const float* b2 = (const float*)d_in[5];
    const float* wl = (const float*)d_in[6];
    const float* bl = (const float*)d_in[7];
    const float* wo = (const float*)d_in[8];
    const float* bo = (const float*)d_in[9];
    float* out = (float*)d_out;

    float* lgts;
    cudaGetSymbolAddress((void**)&lgts, g_logits);

    const int smem_bytes = SMEM_FLOATS * (int)sizeof(float);  // 102080
    cudaFuncSetAttribute(mlp_kernel, cudaFuncAttributeMaxDynamicSharedMemorySize, smem_bytes);

    mlp_kernel<<<B_ROWS / TM, 256, smem_bytes>>>(x, w1, b1, w2, b2, wl, bl, lgts);
    sample_kernel<<<B_ROWS / 8, 256>>>(x, un, lgts, wo, bo,
                                       out, out + (size_t)B_ROWS * 2);
}